// round 9
// baseline (speedup 1.0000x reference)
#include <cuda_runtime.h>
#include <cuda_bf16.h>
#include <cstdint>

#define CH    512
#define HW    4096
#define SCALE (1.0e6f / 33554432.0f)
#define NGEMM 72
#define NSCTA 256
#define NCTA  (NGEMM + NSCTA)

__device__ __align__(16) __nv_bfloat16 g_feats[CH * HW];  // 4 MB bf16 feats
__device__ __align__(16) float g_G[CH * CH];              // gram (scaled 1/2^20)
__device__ unsigned int g_barA;   // convert barrier (monotonic, +NCTA per launch)
__device__ unsigned int g_barB;   // full barrier    (monotonic, +NCTA per launch)

// ---------------------------------------------------------------------------
__device__ __forceinline__ uint32_t smem_u32(const void* p) {
    return static_cast<uint32_t>(__cvta_generic_to_shared(p));
}
__device__ __forceinline__ void cp_async16(uint32_t dst, const void* src) {
    asm volatile("cp.async.cg.shared.global [%0], [%1], 16;\n" :: "r"(dst), "l"(src));
}
template <int N>
__device__ __forceinline__ void cp_wait() {
    asm volatile("cp.async.wait_group %0;\n" :: "n"(N) : "memory");
}
__device__ __forceinline__ void cp_commit() {
    asm volatile("cp.async.commit_group;\n" ::: "memory");
}
__device__ __forceinline__ void ldm_x4(uint32_t* d, uint32_t addr) {
    asm volatile("ldmatrix.sync.aligned.m8n8.x4.shared.b16 {%0,%1,%2,%3}, [%4];"
                 : "=r"(d[0]), "=r"(d[1]), "=r"(d[2]), "=r"(d[3]) : "r"(addr));
}
__device__ __forceinline__ void mma_bf16(float* c, const uint32_t* a, uint32_t b0, uint32_t b1) {
    asm volatile("mma.sync.aligned.m16n8k16.row.col.f32.bf16.bf16.f32 "
                 "{%0,%1,%2,%3},{%4,%5,%6,%7},{%8,%9},{%0,%1,%2,%3};"
                 : "+f"(c[0]), "+f"(c[1]), "+f"(c[2]), "+f"(c[3])
                 : "r"(a[0]), "r"(a[1]), "r"(a[2]), "r"(a[3]), "r"(b0), "r"(b1));
}
__device__ __forceinline__ void spin_to(unsigned int* ctr, unsigned tgt) {
    unsigned cur;
    do {
        __nanosleep(64);
        asm volatile("ld.acquire.gpu.u32 %0, [%1];" : "=r"(cur) : "l"(ctr));
    } while (cur < tgt);
}

// smem 48KB:
//  GEMM: A[2][64][144B] @0 (18432), B[2][64][144B] @18432 (total 36864)
//  S:    ring 3 slots x 16KB (slot = [2 r-halves][8 rows][256 floats])
//  post-barrier: red[16] reuse @0
__global__ void __launch_bounds__(512, 3) k_all(const float* __restrict__ x,
                                                const float* __restrict__ target,
                                                float* __restrict__ out) {
    __shared__ __align__(16) char sm[49152];
    const int t = threadIdx.x;
    const int w = t >> 5, l = t & 31;
    const int bid = blockIdx.x;

    // ============ Phase 1: convert x -> bf16 (all CTAs), zero G ============
    const int gi = bid * 512 + t;                  // 0..167935
    for (int idx = gi; idx < 524288; idx += NCTA * 512) {
        float4 v = reinterpret_cast<const float4*>(x)[idx];
        __nv_bfloat162 p0, p1;
        p0.x = __float2bfloat16(v.x); p0.y = __float2bfloat16(v.y);
        p1.x = __float2bfloat16(v.z); p1.y = __float2bfloat16(v.w);
        uint2 pk;
        pk.x = *reinterpret_cast<uint32_t*>(&p0);
        pk.y = *reinterpret_cast<uint32_t*>(&p1);
        reinterpret_cast<uint2*>(g_feats)[idx] = pk;
    }
    if (gi < 65536)
        reinterpret_cast<float4*>(g_G)[gi] = make_float4(0.f, 0.f, 0.f, 0.f);
    if (gi == 0) out[0] = 0.0f;

    __threadfence();
    __syncthreads();
    if (t == 0) {
        unsigned old = atomicAdd(&g_barA, 1u);
        if (bid < NGEMM) {                  // only GEMM CTAs wait for convert
            unsigned tgt = old - (old % NCTA) + NCTA;
            spin_to(&g_barA, tgt);
        }
    }

    if (bid < NGEMM) {
        // ====== GEMM: upper-tri 64x64 tiles, splitK 2, 16 warps/CTA ======
        __syncthreads();
        const int tile = bid % 36;
        const int kz   = (bid / 36) * 2048;
        int rem = tile, bi = 0;
        while (rem >= 8 - bi) { rem -= 8 - bi; bi++; }
        const int bj = bi + rem;
        const int m0 = bi * 64, n0 = bj * 64;

        const int wm = (w >> 2) * 16;   // 0,16,32,48
        const int wn = (w & 3) * 16;    // 0,16,32,48

        float acc[2][4];
        #pragma unroll
        for (int h = 0; h < 2; h++)
            #pragma unroll
            for (int q = 0; q < 4; q++) acc[h][q] = 0.f;

        const int lr = t >> 3;           // 0..63
        const int lc = (t & 7) * 8;      // bf16 col (16B chunks)
        const int lrow = l & 15;
        const int lkh  = (l >> 4) * 8;
        const uint32_t smA = smem_u32(sm);
        const uint32_t smB = smA + 18432;

        auto load_stage = [&](int ks, int buf) {
            const int kb = kz + ks * 64;
            cp_async16(smA + buf * 9216 + lr * 144 + lc * 2,
                       &g_feats[(m0 + lr) * HW + kb + lc]);
            cp_async16(smB + buf * 9216 + lr * 144 + lc * 2,
                       &g_feats[(n0 + lr) * HW + kb + lc]);
            cp_commit();
        };

        load_stage(0, 0);
        for (int ks = 0; ks < 32; ks++) {
            const int buf = ks & 1;
            if (ks < 31) {
                load_stage(ks + 1, buf ^ 1);
                cp_wait<1>();
            } else {
                cp_wait<0>();
            }
            __syncthreads();

            #pragma unroll
            for (int k16 = 0; k16 < 4; k16++) {
                uint32_t afr[4], bfr[4];
                ldm_x4(afr, smA + buf * 9216 + (wm + lrow) * 144
                                + (k16 * 16 + lkh) * 2);
                ldm_x4(bfr, smB + buf * 9216 + (wn + lrow) * 144
                                + (k16 * 16 + lkh) * 2);
                mma_bf16(acc[0], afr, bfr[0], bfr[2]);
                mma_bf16(acc[1], afr, bfr[1], bfr[3]);
            }
            __syncthreads();
        }

        const float s = 1.0f / 1048576.0f;
        const int g2 = l >> 2, cc = (l & 3) * 2;
        const bool mirror = (bi != bj);
        #pragma unroll
        for (int h = 0; h < 2; h++) {
            const int row = m0 + wm + g2;
            const int col = n0 + wn + h * 8 + cc;
            const float v0 = acc[h][0] * s;
            const float v1 = acc[h][1] * s;
            const float v2 = acc[h][2] * s;
            const float v3 = acc[h][3] * s;
            atomicAdd(&g_G[row * CH + col],           v0);
            atomicAdd(&g_G[row * CH + col + 1],       v1);
            atomicAdd(&g_G[(row + 8) * CH + col],     v2);
            atomicAdd(&g_G[(row + 8) * CH + col + 1], v3);
            if (mirror) {
                atomicAdd(&g_G[col * CH + row],           v0);
                atomicAdd(&g_G[(col + 1) * CH + row],     v1);
                atomicAdd(&g_G[col * CH + row + 8],       v2);
                atomicAdd(&g_G[(col + 1) * CH + row + 8], v3);
            }
        }

        __threadfence();
        __syncthreads();
        if (t == 0) atomicAdd(&g_barB, 1u);      // arrive, no spin, done
        return;
    }

    // ====== S-stream: 2 r-rows per CTA, 3-slot cp.async ring (16KB slots) ======
    const int sb   = bid - NGEMM;            // 0..255
    const int half = t >> 8;                 // 0/1 -> which r this thread serves
    const int tt   = t & 255;
    const int r    = 2 * sb + half;
    const int base = (tt - r) & 511;

    // producer mapping: warp w serves r' = 2*sb + (w>>3), row (w&7) of each stage
    const int pw_half = w >> 3;
    const int pw_row  = w & 7;
    const int rp      = 2 * sb + pw_half;
    const uint32_t stg_u = smem_u32(sm);
    const float* stg = reinterpret_cast<const float*>(sm);

    float Slo = 0.f, Shi = 0.f, T2a = 0.f, T2b = 0.f;

    #define ISSUE(S, SLOT) do {                                              \
        const int j_ = (S) * 8 + pw_row;                                     \
        const int i_ = (rp - j_) & 511;                                      \
        const float* src_ = target + (i_ << 16) + (j_ << 8) + l * 8;         \
        const uint32_t dst_ = stg_u + (SLOT) * 16384 + pw_half * 8192        \
                            + pw_row * 1024 + l * 32;                        \
        cp_async16(dst_, src_);                                              \
        cp_async16(dst_ + 16, src_ + 4);                                     \
        cp_commit();                                                         \
    } while (0)

    ISSUE(0, 0);
    ISSUE(1, 1);
    int islot = 2, cslot = 0;

    #pragma unroll 1
    for (int s = 0; s < 32; s++) {
        if (s < 31) cp_wait<1>(); else cp_wait<0>();
        __syncthreads();                 // stage s ready; all warps done with s-1
        if (s + 2 < 32) {
            ISSUE(s + 2, islot);
            islot = (islot == 2) ? 0 : islot + 1;
        }

        const float* buf = stg + cslot * 4096 + half * 2048;
        cslot = (cslot == 2) ? 0 : cslot + 1;
        int kk = (base + s * 8) & 511;
        #pragma unroll
        for (int xx = 0; xx < 8; xx++) {
            const float v = buf[xx * 256 + (kk & 255)];
            if (xx & 1) T2b = fmaf(v, v, T2b); else T2a = fmaf(v, v, T2a);
            if (kk >> 8) Shi += v; else Slo += v;
            kk = (kk + 1) & 511;
        }
    }
    #undef ISSUE

    // ====== full barrier, then in-place combine vs G row r ======
    __syncthreads();
    if (t == 0) {
        unsigned old = atomicAdd(&g_barB, 1u);
        unsigned tgt = old - (old % NCTA) + NCTA;
        spin_to(&g_barB, tgt);
    }
    __syncthreads();

    const float Gl = g_G[r * CH + tt];
    const float Gh = g_G[r * CH + tt + 256];
    const int d1 = (r - tt) & 511;
    const int d2 = (r - tt - 256) & 511;
    const float m1 = (float)((d1 <= 256) ? 256 - d1 : d1 - 256);
    const float m2 = (float)((d2 <= 256) ? 256 - d2 : d2 - 256);
    float term = fmaf(m1 * Gl, Gl, -2.0f * Gl * Slo)
               + fmaf(m2 * Gh, Gh, -2.0f * Gh * Shi)
               + T2a + T2b;

    #pragma unroll
    for (int o = 16; o > 0; o >>= 1)
        term += __shfl_xor_sync(0xFFFFFFFFu, term, o);
    float* red = reinterpret_cast<float*>(sm);
    if (l == 0) red[w] = term;
    __syncthreads();
    if (t == 0) {
        float z = 0.f;
        #pragma unroll
        for (int ww = 0; ww < 16; ww++) z += red[ww];
        atomicAdd(out, z * SCALE);
    }
}

// ---------------------------------------------------------------------------
extern "C" void kernel_launch(void* const* d_in, const int* in_sizes, int n_in,
                              void* d_out, int out_size) {
    const float* x      = (const float*)d_in[0];   // (1,512,64,64) fp32
    const float* target = (const float*)d_in[1];   // (512,256,256) fp32
    float* out = (float*)d_out;

    k_all<<<NCTA, 512>>>(x, target, out);
}

// round 10
// speedup vs baseline: 1.1213x; 1.1213x over previous
#include <cuda_runtime.h>
#include <cuda_bf16.h>
#include <cstdint>

#define CH     512
#define HW     4096
#define SCALE  (1.0e6f / 33554432.0f)
#define NGEMM  72
#define NSCTA  512
#define NCTA   (NGEMM + NSCTA)
#define NUNITS 2048   // (row r: 0..511) x (quarter q: 0..3), 64 j's each

__device__ __align__(16) __nv_bfloat16 g_feats[CH * HW];  // 4 MB bf16 feats
__device__ __align__(16) float g_G[CH * CH];              // gram (scaled 1/2^20)
__device__ __align__(16) float g_S[CH * CH];              // S (atomic partial sums)
__device__ float g_T2acc;                                 // sum of T^2 (reset per launch)
__device__ unsigned int g_work;                           // ticket ctr (reset per launch)
__device__ unsigned int g_barA;   // monotonic, +NCTA per launch
__device__ unsigned int g_barB;   // monotonic, +NCTA per launch

// ---------------------------------------------------------------------------
__device__ __forceinline__ uint32_t smem_u32(const void* p) {
    return static_cast<uint32_t>(__cvta_generic_to_shared(p));
}
__device__ __forceinline__ void cp_async16(uint32_t dst, const void* src) {
    asm volatile("cp.async.cg.shared.global [%0], [%1], 16;\n" :: "r"(dst), "l"(src));
}
template <int N>
__device__ __forceinline__ void cp_wait() {
    asm volatile("cp.async.wait_group %0;\n" :: "n"(N) : "memory");
}
__device__ __forceinline__ void cp_commit() {
    asm volatile("cp.async.commit_group;\n" ::: "memory");
}
__device__ __forceinline__ void ldm_x4(uint32_t* d, uint32_t addr) {
    asm volatile("ldmatrix.sync.aligned.m8n8.x4.shared.b16 {%0,%1,%2,%3}, [%4];"
                 : "=r"(d[0]), "=r"(d[1]), "=r"(d[2]), "=r"(d[3]) : "r"(addr));
}
__device__ __forceinline__ void mma_bf16(float* c, const uint32_t* a, uint32_t b0, uint32_t b1) {
    asm volatile("mma.sync.aligned.m16n8k16.row.col.f32.bf16.bf16.f32 "
                 "{%0,%1,%2,%3},{%4,%5,%6,%7},{%8,%9},{%0,%1,%2,%3};"
                 : "+f"(c[0]), "+f"(c[1]), "+f"(c[2]), "+f"(c[3])
                 : "r"(a[0]), "r"(a[1]), "r"(a[2]), "r"(a[3]), "r"(b0), "r"(b1));
}
__device__ __forceinline__ void spin_to(unsigned int* ctr, unsigned tgt) {
    unsigned cur;
    do {
        __nanosleep(64);
        asm volatile("ld.acquire.gpu.u32 %0, [%1];" : "=r"(cur) : "l"(ctr));
    } while (cur < tgt);
}

// smem 36928B: GEMM A[2][64][144B]@0, B[2][64][144B]@18432 (36864 total)
//              S ring: 4 slots x 8KB @0 (32768)
//              tk_slot int @36864, red[8] floats @36868
__global__ void __launch_bounds__(256, 4) k_all(const float* __restrict__ x,
                                                const float* __restrict__ target,
                                                float* __restrict__ out) {
    __shared__ __align__(16) char sm[36928];
    int*   tk_slot = reinterpret_cast<int*>(sm + 36864);
    float* red     = reinterpret_cast<float*>(sm + 36868);
    const int t = threadIdx.x;
    const int w = t >> 5, l = t & 31;
    const int bid = blockIdx.x;

    // ============ Phase 1: convert x -> bf16 (all CTAs), zero G & S ============
    const int gi = bid * 256 + t;                  // 0..149503
    for (int idx = gi; idx < 524288; idx += NCTA * 256) {
        float4 v = reinterpret_cast<const float4*>(x)[idx];
        __nv_bfloat162 p0, p1;
        p0.x = __float2bfloat16(v.x); p0.y = __float2bfloat16(v.y);
        p1.x = __float2bfloat16(v.z); p1.y = __float2bfloat16(v.w);
        uint2 pk;
        pk.x = *reinterpret_cast<uint32_t*>(&p0);
        pk.y = *reinterpret_cast<uint32_t*>(&p1);
        reinterpret_cast<uint2*>(g_feats)[idx] = pk;
    }
    if (gi < 65536)
        reinterpret_cast<float4*>(g_G)[gi] = make_float4(0.f, 0.f, 0.f, 0.f);
    else if (gi < 131072)
        reinterpret_cast<float4*>(g_S)[gi - 65536] = make_float4(0.f, 0.f, 0.f, 0.f);
    if (gi == 0) out[0] = 0.0f;

    __threadfence();
    __syncthreads();
    unsigned tgtA = 0;
    if (t == 0) {
        unsigned old = atomicAdd(&g_barA, 1u);
        tgtA = old - (old % NCTA) + NCTA;
        if (bid < NGEMM) spin_to(&g_barA, tgtA);   // GEMM needs feats now
    }
    bool needA = (bid >= NGEMM);                   // S CTAs defer barA to 1st flush

    if (bid < NGEMM) {
        // ====== GEMM: upper-tri 64x64 tiles, splitK 2 (R7-proven) ======
        __syncthreads();
        const int tile = bid % 36;
        const int kz   = (bid / 36) * 2048;
        int rem = tile, bi = 0;
        while (rem >= 8 - bi) { rem -= 8 - bi; bi++; }
        const int bj = bi + rem;
        const int m0 = bi * 64, n0 = bj * 64;

        const int wm = (w >> 2) * 32;
        const int wn = (w & 3) * 16;

        float acc[2][2][4];
        #pragma unroll
        for (int a = 0; a < 2; a++)
          #pragma unroll
          for (int h = 0; h < 2; h++)
            #pragma unroll
            for (int q = 0; q < 4; q++) acc[a][h][q] = 0.f;

        const int lr = t >> 3;
        const int lc = (t & 7) * 8;
        const int lrow = l & 15;
        const int lkh  = (l >> 4) * 8;
        const uint32_t smA = smem_u32(sm);
        const uint32_t smB = smA + 18432;

        auto load_stage = [&](int ks, int buf) {
            const int kb = kz + ks * 64;
            #pragma unroll
            for (int p = 0; p < 2; p++) {
                const int row = lr + p * 32;
                cp_async16(smA + buf * 9216 + row * 144 + lc * 2,
                           &g_feats[(m0 + row) * HW + kb + lc]);
                cp_async16(smB + buf * 9216 + row * 144 + lc * 2,
                           &g_feats[(n0 + row) * HW + kb + lc]);
            }
            cp_commit();
        };

        load_stage(0, 0);
        for (int ks = 0; ks < 32; ks++) {
            const int buf = ks & 1;
            if (ks < 31) {
                load_stage(ks + 1, buf ^ 1);
                cp_wait<1>();
            } else {
                cp_wait<0>();
            }
            __syncthreads();

            #pragma unroll
            for (int k16 = 0; k16 < 4; k16++) {
                uint32_t afr[2][4], bfr[4];
                #pragma unroll
                for (int mt = 0; mt < 2; mt++)
                    ldm_x4(afr[mt], smA + buf * 9216 + (wm + mt * 16 + lrow) * 144
                                        + (k16 * 16 + lkh) * 2);
                ldm_x4(bfr, smB + buf * 9216 + (wn + lrow) * 144
                                + (k16 * 16 + lkh) * 2);
                #pragma unroll
                for (int mt = 0; mt < 2; mt++) {
                    mma_bf16(acc[mt][0], afr[mt], bfr[0], bfr[2]);
                    mma_bf16(acc[mt][1], afr[mt], bfr[1], bfr[3]);
                }
            }
            __syncthreads();
        }

        const float s = 1.0f / 1048576.0f;
        const int g2 = l >> 2, cc = (l & 3) * 2;
        const bool mirror = (bi != bj);
        #pragma unroll
        for (int mt = 0; mt < 2; mt++)
          #pragma unroll
          for (int h = 0; h < 2; h++) {
            const int row = m0 + wm + mt * 16 + g2;
            const int col = n0 + wn + h * 8 + cc;
            const float v0 = acc[mt][h][0] * s;
            const float v1 = acc[mt][h][1] * s;
            const float v2 = acc[mt][h][2] * s;
            const float v3 = acc[mt][h][3] * s;
            atomicAdd(&g_G[row * CH + col],           v0);
            atomicAdd(&g_G[row * CH + col + 1],       v1);
            atomicAdd(&g_G[(row + 8) * CH + col],     v2);
            atomicAdd(&g_G[(row + 8) * CH + col + 1], v3);
            if (mirror) {
                atomicAdd(&g_G[col * CH + row],           v0);
                atomicAdd(&g_G[(col + 1) * CH + row],     v1);
                atomicAdd(&g_G[col * CH + row + 8],       v2);
                atomicAdd(&g_G[(col + 1) * CH + row + 8], v3);
            }
          }

        __threadfence();
        __syncthreads();      // smem safe to reuse as S ring
    }

    // ====== Work-stealing S-stream: units = (r, quarter of 64 j's) ======
    const int xr = t >> 5;                    // producer row within stage
    const uint32_t stg_u = smem_u32(sm);
    const float* stg = reinterpret_cast<const float*>(sm);
    float T2a = 0.f, T2b = 0.f;

    while (true) {
        if (t == 0) *tk_slot = (int)atomicAdd(&g_work, 1u);
        __syncthreads();
        const int tk = *tk_slot;
        __syncthreads();
        if (tk >= NUNITS) break;

        const int r   = tk >> 2;
        const int jb0 = (tk & 3) * 64;
        const int base = (t - r) & 511;
        float Slo = 0.f, Shi = 0.f;

        #define ISSUE(S) do {                                                \
            const int j_ = jb0 + (S) * 8 + xr;                               \
            const int i_ = (r - j_) & 511;                                   \
            const float* src_ = target + (i_ << 16) + (j_ << 8) + l * 8;     \
            const uint32_t dst_ = stg_u + ((S) & 3) * 8192 + xr * 1024       \
                                + l * 32;                                    \
            cp_async16(dst_, src_);                                          \
            cp_async16(dst_ + 16, src_ + 4);                                 \
            cp_commit();                                                     \
        } while (0)

        ISSUE(0); ISSUE(1); ISSUE(2);
        #pragma unroll 1
        for (int s = 0; s < 8; s++) {
            if (s < 6)       cp_wait<2>();
            else if (s == 6) cp_wait<1>();
            else             cp_wait<0>();
            __syncthreads();
            if (s < 5) ISSUE(s + 3);

            const float* buf = stg + (s & 3) * 2048;
            int kk = (base + jb0 + s * 8) & 511;
            #pragma unroll
            for (int xx = 0; xx < 8; xx++) {
                const float v = buf[xx * 256 + (kk & 255)];
                if (xx & 1) T2b = fmaf(v, v, T2b); else T2a = fmaf(v, v, T2a);
                if (kk >> 8) Shi += v; else Slo += v;
                kk = (kk + 1) & 511;
            }
        }
        #undef ISSUE

        if (needA) {                      // ensure g_S zeroing done before 1st flush
            if (t == 0) spin_to(&g_barA, tgtA);
            __syncthreads();
            needA = false;
        }
        atomicAdd(&g_S[(r << 9) + t],       Slo);
        atomicAdd(&g_S[(r << 9) + 256 + t], Shi);
    }

    // flush T2 (block reduce, one atomic per CTA)
    float T2 = T2a + T2b;
    #pragma unroll
    for (int o = 16; o > 0; o >>= 1)
        T2 += __shfl_xor_sync(0xFFFFFFFFu, T2, o);
    if (l == 0) red[w] = T2;
    __syncthreads();
    if (t == 0) {
        float z = 0.f;
        #pragma unroll
        for (int ww = 0; ww < 8; ww++) z += red[ww];
        atomicAdd(&g_T2acc, z);
    }

    // ====== full barrier, then combine ======
    __threadfence();
    __syncthreads();
    if (t == 0) {
        unsigned old = atomicAdd(&g_barB, 1u);
        unsigned tgt = old - (old % NCTA) + NCTA;
        if (bid == 0 || bid >= NGEMM) spin_to(&g_barB, tgt);
    }
    if (bid > 0 && bid < NGEMM) return;       // arrived; no post-work
    __syncthreads();

    if (bid == 0) {
        if (t == 0) {
            atomicAdd(out, g_T2acc * SCALE);
            g_T2acc = 0.0f;                   // reset per-launch state
            g_work  = 0u;
        }
        return;
    }

    // combine row r = bid - NGEMM
    const int r = bid - NGEMM;
    const float Gl = g_G[(r << 9) + t];
    const float Gh = g_G[(r << 9) + t + 256];
    const float Sl = g_S[(r << 9) + t];
    const float Sh = g_S[(r << 9) + t + 256];
    const int d1 = (r - t) & 511;
    const int d2 = (r - t - 256) & 511;
    const float m1 = (float)((d1 <= 256) ? 256 - d1 : d1 - 256);
    const float m2 = (float)((d2 <= 256) ? 256 - d2 : d2 - 256);
    float term = fmaf(m1 * Gl, Gl, -2.0f * Gl * Sl)
               + fmaf(m2 * Gh, Gh, -2.0f * Gh * Sh);

    #pragma unroll
    for (int o = 16; o > 0; o >>= 1)
        term += __shfl_xor_sync(0xFFFFFFFFu, term, o);
    if (l == 0) red[w] = term;
    __syncthreads();
    if (t == 0) {
        float z = 0.f;
        #pragma unroll
        for (int ww = 0; ww < 8; ww++) z += red[ww];
        atomicAdd(out, z * SCALE);
    }
}

// ---------------------------------------------------------------------------
extern "C" void kernel_launch(void* const* d_in, const int* in_sizes, int n_in,
                              void* d_out, int out_size) {
    const float* x      = (const float*)d_in[0];   // (1,512,64,64) fp32
    const float* target = (const float*)d_in[1];   // (512,256,256) fp32
    float* out = (float*)d_out;

    k_all<<<NCTA, 256>>>(x, target, out);
}

// round 11
// speedup vs baseline: 1.1692x; 1.0427x over previous
#include <cuda_runtime.h>
#include <cuda_bf16.h>
#include <cstdint>

#define CH     512
#define HW     4096
#define SCALE  (1.0e6f / 33554432.0f)
#define NGEMM  272    // 136 upper-tri 32x32 tiles x splitK 2
#define NSCTA  512
#define NCTA   (NGEMM + NSCTA)
#define NUNITS 2048   // (row r) x (quarter of j), 64 j's each

__device__ __align__(16) __nv_bfloat16 g_feats[CH * HW];  // 4 MB bf16 feats
__device__ __align__(16) float g_G[CH * CH];              // gram (scaled 1/2^20)
__device__ __align__(16) float g_S[CH * CH];              // S (atomic partial sums)
__device__ float g_T2acc;                                 // sum T^2 (reset per launch)
__device__ unsigned int g_work;                           // ticket ctr (reset per launch)
__device__ unsigned int g_barA;   // monotonic, +NCTA per launch
__device__ unsigned int g_barB;   // monotonic, +NCTA per launch

// ---------------------------------------------------------------------------
__device__ __forceinline__ uint32_t smem_u32(const void* p) {
    return static_cast<uint32_t>(__cvta_generic_to_shared(p));
}
__device__ __forceinline__ void cp_async16(uint32_t dst, const void* src) {
    asm volatile("cp.async.cg.shared.global [%0], [%1], 16;\n" :: "r"(dst), "l"(src));
}
template <int N>
__device__ __forceinline__ void cp_wait() {
    asm volatile("cp.async.wait_group %0;\n" :: "n"(N) : "memory");
}
__device__ __forceinline__ void cp_commit() {
    asm volatile("cp.async.commit_group;\n" ::: "memory");
}
__device__ __forceinline__ void ldm_x4(uint32_t* d, uint32_t addr) {
    asm volatile("ldmatrix.sync.aligned.m8n8.x4.shared.b16 {%0,%1,%2,%3}, [%4];"
                 : "=r"(d[0]), "=r"(d[1]), "=r"(d[2]), "=r"(d[3]) : "r"(addr));
}
__device__ __forceinline__ void ldm_x2(uint32_t* d, uint32_t addr) {
    asm volatile("ldmatrix.sync.aligned.m8n8.x2.shared.b16 {%0,%1}, [%2];"
                 : "=r"(d[0]), "=r"(d[1]) : "r"(addr));
}
__device__ __forceinline__ void mma_bf16(float* c, const uint32_t* a, uint32_t b0, uint32_t b1) {
    asm volatile("mma.sync.aligned.m16n8k16.row.col.f32.bf16.bf16.f32 "
                 "{%0,%1,%2,%3},{%4,%5,%6,%7},{%8,%9},{%0,%1,%2,%3};"
                 : "+f"(c[0]), "+f"(c[1]), "+f"(c[2]), "+f"(c[3])
                 : "r"(a[0]), "r"(a[1]), "r"(a[2]), "r"(a[3]), "r"(b0), "r"(b1));
}
__device__ __forceinline__ void spin_to(unsigned int* ctr, unsigned tgt) {
    unsigned cur;
    do {
        __nanosleep(64);
        asm volatile("ld.acquire.gpu.u32 %0, [%1];" : "=r"(cur) : "l"(ctr));
    } while (cur < tgt);
}

// smem 24576B total (3 CTAs... 7 CTAs/SM @ 24KB):
//  GEMM: 3 slots x 8KB; slot = A(32x128B, XOR-swizzled) @0 + B @4096
//  S:    3 slots x 8KB linear ([8 rows][256 floats])
//  tk_slot @0 (int), red[8] @4..36 — phase-disjoint aliases of slot 0
__global__ void __launch_bounds__(256, 7) k_all(const float* __restrict__ x,
                                                const float* __restrict__ target,
                                                float* __restrict__ out) {
    __shared__ __align__(16) char sm[24576];
    int*   tk_slot = reinterpret_cast<int*>(sm);
    float* red     = reinterpret_cast<float*>(sm + 4);
    const int t = threadIdx.x;
    const int w = t >> 5, l = t & 31;
    const int bid = blockIdx.x;

    // ============ Phase 1: convert x -> bf16 (all CTAs), zero G & S ============
    const int gi = bid * 256 + t;
    for (int idx = gi; idx < 524288; idx += NCTA * 256) {
        float4 v = reinterpret_cast<const float4*>(x)[idx];
        __nv_bfloat162 p0, p1;
        p0.x = __float2bfloat16(v.x); p0.y = __float2bfloat16(v.y);
        p1.x = __float2bfloat16(v.z); p1.y = __float2bfloat16(v.w);
        uint2 pk;
        pk.x = *reinterpret_cast<uint32_t*>(&p0);
        pk.y = *reinterpret_cast<uint32_t*>(&p1);
        reinterpret_cast<uint2*>(g_feats)[idx] = pk;
    }
    if (gi < 65536)
        reinterpret_cast<float4*>(g_G)[gi] = make_float4(0.f, 0.f, 0.f, 0.f);
    else if (gi < 131072)
        reinterpret_cast<float4*>(g_S)[gi - 65536] = make_float4(0.f, 0.f, 0.f, 0.f);
    if (gi == 0) out[0] = 0.0f;

    __threadfence();
    __syncthreads();
    unsigned tgtA = 0;
    if (t == 0) {
        unsigned old = atomicAdd(&g_barA, 1u);
        tgtA = old - (old % NCTA) + NCTA;
        if (bid < NGEMM) spin_to(&g_barA, tgtA);   // GEMM needs feats now
    }
    bool needA = (bid >= NGEMM);                   // S CTAs defer to first flush

    if (bid < NGEMM) {
        // ====== GEMM: 32x32 upper-tri tiles, splitK 2, 8 warps, 28-reg class ======
        __syncthreads();
        const int tile = bid % 136;
        const int kz   = (bid / 136) * 2048;
        int rem = tile, bi = 0;
        while (rem >= 16 - bi) { rem -= 16 - bi; bi++; }
        const int bj = bi + rem;
        const int m0 = bi * 32, n0 = bj * 32;

        const int wm = (w >> 2) * 16;    // 0,16
        const int wn = (w & 3) * 8;      // 0,8,16,24

        float acc[4];
        acc[0] = acc[1] = acc[2] = acc[3] = 0.f;

        const int lrow = l & 15;
        const int lkh2 = (l >> 4) * 16;          // byte offset for A k-half
        const int rb   = wn + (l & 7);           // B row (lanes 0-15 used)
        const int cbB0 = ((l >> 3) & 1) * 16;    // B k-half bytes
        const uint32_t smb = smem_u32(sm);

        const int srow = t >> 3;                 // 0..31
        const int sc16 = (t & 7) * 16;           // byte col
        const uint32_t sdst = (uint32_t)(((srow * 128 + sc16) ^ ((srow & 7) << 4)));

        #define GLOAD(KS, SL) do {                                           \
            const int kb_ = kz + (KS) * 64;                                  \
            cp_async16(smb + (SL) * 8192 + sdst,                             \
                       &g_feats[(m0 + srow) * HW + kb_ + (t & 7) * 8]);      \
            cp_async16(smb + (SL) * 8192 + 4096 + sdst,                      \
                       &g_feats[(n0 + srow) * HW + kb_ + (t & 7) * 8]);      \
            cp_commit();                                                     \
        } while (0)

        GLOAD(0, 0);
        GLOAD(1, 1);
        for (int ks = 0; ks < 32; ks++) {
            if (ks < 31) cp_wait<1>(); else cp_wait<0>();
            __syncthreads();
            if (ks < 30) GLOAD(ks + 2, (ks + 2) % 3);

            const uint32_t slot = smb + (ks % 3) * 8192;
            #pragma unroll
            for (int k16 = 0; k16 < 4; k16++) {
                uint32_t afr[4], bfr[2];
                const int ra = wm + lrow;
                const int cbA = k16 * 32 + lkh2;
                ldm_x4(afr, slot + (uint32_t)((ra * 128 + cbA) ^ ((ra & 7) << 4)));
                const int cbB = k16 * 32 + cbB0;
                ldm_x2(bfr, slot + 4096 + (uint32_t)((rb * 128 + cbB) ^ ((rb & 7) << 4)));
                mma_bf16(acc, afr, bfr[0], bfr[1]);
            }
        }
        #undef GLOAD

        const float s = 1.0f / 1048576.0f;
        const int g2 = l >> 2, cc = (l & 3) * 2;
        const bool mirror = (bi != bj);
        {
            const int row = m0 + wm + g2;
            const int col = n0 + wn + cc;
            const float v0 = acc[0] * s, v1 = acc[1] * s;
            const float v2 = acc[2] * s, v3 = acc[3] * s;
            atomicAdd(&g_G[row * CH + col],           v0);
            atomicAdd(&g_G[row * CH + col + 1],       v1);
            atomicAdd(&g_G[(row + 8) * CH + col],     v2);
            atomicAdd(&g_G[(row + 8) * CH + col + 1], v3);
            if (mirror) {
                atomicAdd(&g_G[col * CH + row],           v0);
                atomicAdd(&g_G[(col + 1) * CH + row],     v1);
                atomicAdd(&g_G[col * CH + row + 8],       v2);
                atomicAdd(&g_G[(col + 1) * CH + row + 8], v3);
            }
        }
        __threadfence();
        __syncthreads();      // smem safe to reuse as S ring
    }

    // ====== Work-stealing S-stream: 3-slot ring, unit = (r, quarter j) ======
    const uint32_t stg_u = smem_u32(sm);
    const float* stg = reinterpret_cast<const float*>(sm);
    float T2a = 0.f, T2b = 0.f;

    while (true) {
        if (t == 0) *tk_slot = (int)atomicAdd(&g_work, 1u);
        __syncthreads();
        const int tk = *tk_slot;
        __syncthreads();
        if (tk >= NUNITS) break;

        const int r   = tk >> 2;
        const int jb0 = (tk & 3) * 64;
        const int base = (t - r) & 511;
        float Slo = 0.f, Shi = 0.f;

        #define ISSUE(S) do {                                                \
            const int j_ = jb0 + (S) * 8 + w;                                \
            const int i_ = (r - j_) & 511;                                   \
            const float* src_ = target + (i_ << 16) + (j_ << 8) + l * 8;     \
            const uint32_t dst_ = stg_u + ((S) % 3) * 8192 + w * 1024        \
                                + l * 32;                                    \
            cp_async16(dst_, src_);                                          \
            cp_async16(dst_ + 16, src_ + 4);                                 \
            cp_commit();                                                     \
        } while (0)

        ISSUE(0); ISSUE(1);
        #pragma unroll 1
        for (int s = 0; s < 8; s++) {
            if (s < 7) cp_wait<1>(); else cp_wait<0>();
            __syncthreads();
            if (s < 6) ISSUE(s + 2);

            const float* buf = stg + (s % 3) * 2048;
            int kk = (base + jb0 + s * 8) & 511;
            #pragma unroll
            for (int xx = 0; xx < 8; xx++) {
                const float v = buf[xx * 256 + (kk & 255)];
                if (xx & 1) T2b = fmaf(v, v, T2b); else T2a = fmaf(v, v, T2a);
                if (kk >> 8) Shi += v; else Slo += v;
                kk = (kk + 1) & 511;
            }
        }
        #undef ISSUE

        if (needA) {                  // g_S zeroing must be done before 1st flush
            if (t == 0) spin_to(&g_barA, tgtA);
            __syncthreads();
            needA = false;
        }
        atomicAdd(&g_S[(r << 9) + t],       Slo);
        atomicAdd(&g_S[(r << 9) + 256 + t], Shi);
    }

    // flush T2 (block reduce, one atomic per CTA)
    float T2 = T2a + T2b;
    #pragma unroll
    for (int o = 16; o > 0; o >>= 1)
        T2 += __shfl_xor_sync(0xFFFFFFFFu, T2, o);
    if (l == 0) red[w] = T2;
    __syncthreads();
    if (t == 0) {
        float z = 0.f;
        #pragma unroll
        for (int ww = 0; ww < 8; ww++) z += red[ww];
        atomicAdd(&g_T2acc, z);
    }

    // ====== full barrier, then combine ======
    __threadfence();
    __syncthreads();
    if (t == 0) {
        unsigned old = atomicAdd(&g_barB, 1u);
        unsigned tgt = old - (old % NCTA) + NCTA;
        if (bid == 0 || bid >= NGEMM) spin_to(&g_barB, tgt);
    }
    if (bid > 0 && bid < NGEMM) return;       // arrived; no post-work
    __syncthreads();

    if (bid == 0) {
        if (t == 0) {
            atomicAdd(out, g_T2acc * SCALE);
            g_T2acc = 0.0f;                   // reset per-launch state
            g_work  = 0u;
        }
        return;
    }

    // combine row r = bid - NGEMM
    const int r = bid - NGEMM;
    const float Gl = g_G[(r << 9) + t];
    const float Gh = g_G[(r << 9) + t + 256];
    const float Sl = g_S[(r << 9) + t];
    const float Sh = g_S[(r << 9) + t + 256];
    const int d1 = (r - t) & 511;
    const int d2 = (r - t - 256) & 511;
    const float m1 = (float)((d1 <= 256) ? 256 - d1 : d1 - 256);
    const float m2 = (float)((d2 <= 256) ? 256 - d2 : d2 - 256);
    float term = fmaf(m1 * Gl, Gl, -2.0f * Gl * Sl)
               + fmaf(m2 * Gh, Gh, -2.0f * Gh * Sh);

    #pragma unroll
    for (int o = 16; o > 0; o >>= 1)
        term += __shfl_xor_sync(0xFFFFFFFFu, term, o);
    if (l == 0) red[w] = term;
    __syncthreads();
    if (t == 0) {
        float z = 0.f;
        #pragma unroll
        for (int ww = 0; ww < 8; ww++) z += red[ww];
        atomicAdd(out, z * SCALE);
    }
}

// ---------------------------------------------------------------------------
extern "C" void kernel_launch(void* const* d_in, const int* in_sizes, int n_in,
                              void* d_out, int out_size) {
    const float* x      = (const float*)d_in[0];   // (1,512,64,64) fp32
    const float* target = (const float*)d_in[1];   // (512,256,256) fp32
    float* out = (float*)d_out;

    k_all<<<NCTA, 256>>>(x, target, out);
}